// round 7
// baseline (speedup 1.0000x reference)
#include <cuda_runtime.h>
#include <cuda_fp16.h>
#include <cstdint>

#define F    128
#define E    16
#define KN   32
#define Q    (E * F)   // 2048
#define MT   12        // nodes per CTA (48B fp32 S rows -> 2 CTAs/SM)
#define NT   256

#define S_FLOATS    (Q * MT)                       // 24576 floats = 98304 B
#define EB_OFF      S_FLOATS
#define EB_FLOATS   (2 * KN * E)                   // 1024
#define IB_OFF_B    ((EB_OFF + EB_FLOATS) * 4)
#define SMEM_BYTES  (IB_OFF_B + 2 * KN * 4)        // 102656 B -> 2 CTAs/SM

// Pre-transposed fp16 weights: W2h[q*128 + m] = (half) w[l*2048 + m*16 + n], q = n*128 + l.
__device__ __half g_W2h[Q * F];
__device__ int g_is64;

// ---------- packed f32x2 helpers ----------
__device__ __forceinline__ void ffma2(unsigned long long& d,
                                      unsigned long long a,
                                      unsigned long long b) {
    asm("fma.rn.f32x2 %0, %1, %2, %0;" : "+l"(d) : "l"(a), "l"(b));
}
__device__ __forceinline__ unsigned long long pk2(float x, float y) {
    unsigned long long r;
    asm("mov.b64 %0, {%1, %2};" : "=l"(r) : "f"(x), "f"(y));
    return r;
}
__device__ __forceinline__ void unpk2(float& x, float& y, unsigned long long v) {
    asm("mov.b64 {%0, %1}, %2;" : "=f"(x), "=f"(y) : "l"(v));
}

// ---------- kernel 1: setup = transpose w -> g_W2h (fp16), plus nlist dtype detect ----------
__global__ void setup_kernel(const float* __restrict__ w,
                             const int* __restrict__ nl) {
    if (blockIdx.x == 0 && threadIdx.x < 32) {
        int odd_nonzero = (threadIdx.x < 16) ? (nl[2 * threadIdx.x + 1] != 0) : 0;
        unsigned any = __ballot_sync(0xffffffffu, odd_nonzero);
        if (threadIdx.x == 0) g_is64 = (any == 0u) ? 1 : 0;
    }
    int o = blockIdx.x * blockDim.x + threadIdx.x;
    if (o >= Q * F) return;
    int m = o & (F - 1);
    int q = o >> 7;
    int l = q & (F - 1);
    int n = q >> 7;
    g_W2h[o] = __float2half_rn(w[((l << 7) + m) * E + n]);
}

// ---------- kernel 2: fused gather + contraction ----------
__global__ void __launch_bounds__(NT, 2)
mp_kernel(const float* __restrict__ nodes,
          const void* __restrict__ nlist_raw,
          const float* __restrict__ edges,
          float* __restrict__ out,
          int N) {
    extern __shared__ float smem[];
    float* S  = smem;                              // [Q][MT] fp32
    float* eb = smem + EB_OFF;                     // [2][KN*E]
    int*   ib = (int*)((char*)smem + IB_OFF_B);    // [2][KN]

    const int tid  = threadIdx.x;
    const int base = blockIdx.x * MT;
    const int is64 = g_is64;

    const long long* nl64 = (const long long*)nlist_raw;
    const int*       nl32 = (const int*)nlist_raw;

    // ===== Stage 1: S[q][v] = sum_j nodes[idx[v][j], l] * edges[base+v, j, n] =====
    {
        const int l   = tid & (F - 1);
        const int sub = tid >> 7;       // 0/1
        for (int it = 0; it < MT / 2; ++it) {
            const int v = it * 2 + sub;
            const int i = base + v;
            const bool valid = (i < N);

            __syncthreads();   // protect previous iteration's eb/ib

            if (valid) {
                ((float4*)(eb + sub * (KN * E)))[l] =
                    ((const float4*)(edges + (size_t)i * (KN * E)))[l];
                if (l < KN) {
                    int nb = is64 ? (int)nl64[(size_t)i * KN + l]
                                  :      nl32[(size_t)i * KN + l];
                    ib[sub * KN + l] = nb;
                }
            }
            __syncthreads();

            if (valid) {
                unsigned long long acc[E / 2];
                #pragma unroll
                for (int p = 0; p < E / 2; ++p) acc[p] = 0ull;

                const float* ebs = eb + sub * (KN * E);
                const int*   ibs = ib + sub * KN;

                #pragma unroll
                for (int j0 = 0; j0 < KN; j0 += 8) {
                    float x[8];
                    #pragma unroll
                    for (int u = 0; u < 8; ++u) {
                        int nb = ibs[j0 + u];
                        x[u] = nodes[(size_t)nb * F + l];   // coalesced over l
                    }
                    #pragma unroll
                    for (int u = 0; u < 8; ++u) {
                        unsigned long long xx = pk2(x[u], x[u]);
                        // edges row for this j: 64B read as 4 broadcast LDS.128
                        const ulonglong2* ep2 =
                            (const ulonglong2*)(ebs + (j0 + u) * E);
                        const ulonglong2 e01 = ep2[0];
                        const ulonglong2 e23 = ep2[1];
                        const ulonglong2 e45 = ep2[2];
                        const ulonglong2 e67 = ep2[3];
                        ffma2(acc[0], xx, e01.x);  ffma2(acc[1], xx, e01.y);
                        ffma2(acc[2], xx, e23.x);  ffma2(acc[3], xx, e23.y);
                        ffma2(acc[4], xx, e45.x);  ffma2(acc[5], xx, e45.y);
                        ffma2(acc[6], xx, e67.x);  ffma2(acc[7], xx, e67.y);
                    }
                }

                #pragma unroll
                for (int p = 0; p < E / 2; ++p) {
                    float a, b;
                    unpk2(a, b, acc[p]);
                    S[((2 * p)     * F + l) * MT + v] = a;
                    S[((2 * p + 1) * F + l) * MT + v] = b;
                }
            }
        }
        __syncthreads();
    }

    // ===== Stage 2: register-tiled GEMM: out[v][m] = (1/K) sum_q S[q][v] * W2[q][m] =====
    // thread = (mg = tid&31 -> m = 4mg..4mg+3; qs = tid>>5 -> q in [qs*256, qs*256+256)).
    // Per q: 1 LDG.64 (W fp16, 4 m) + 3 broadcast LDS.128 (12 nodes) + 4 cvt + 4 pk2 -> 24 FFMA2.
    const int mg = tid & 31;
    const int qs = tid >> 5;
    const uint2* Wh2 = ((const uint2*)g_W2h) + mg;   // + q*32 (8B per q per thread)
    const float* Sh  = S + (qs << 8) * MT;

    unsigned long long acc[4][6];   // [m'][node-pair]
    #pragma unroll
    for (int mp = 0; mp < 4; ++mp)
        #pragma unroll
        for (int p = 0; p < 6; ++p) acc[mp][p] = 0ull;

    #pragma unroll 1
    for (int q0 = 0; q0 < 256; q0 += 8) {
        uint2 wv[8];
        #pragma unroll
        for (int u = 0; u < 8; ++u)
            wv[u] = Wh2[(size_t)(((qs << 8) + q0 + u) << 5)];   // 8 coalesced LDG.64 in flight
        #pragma unroll
        for (int u = 0; u < 8; ++u) {
            const float* row = Sh + (q0 + u) * MT;
            const ulonglong2 sA = *(const ulonglong2*)(row);       // nodes 0..3
            const ulonglong2 sB = *(const ulonglong2*)(row + 4);   // nodes 4..7
            const ulonglong2 sC = *(const ulonglong2*)(row + 8);   // nodes 8..11
            const unsigned long long s[6] = {sA.x, sA.y, sB.x, sB.y, sC.x, sC.y};
            const float2 f01 = __half22float2(*(const __half2*)&wv[u].x);
            const float2 f23 = __half22float2(*(const __half2*)&wv[u].y);
            unsigned long long wp[4];
            wp[0] = pk2(f01.x, f01.x);
            wp[1] = pk2(f01.y, f01.y);
            wp[2] = pk2(f23.x, f23.x);
            wp[3] = pk2(f23.y, f23.y);
            #pragma unroll
            for (int mp = 0; mp < 4; ++mp)
                #pragma unroll
                for (int p = 0; p < 6; ++p)
                    ffma2(acc[mp][p], s[p], wp[mp]);
        }
    }

    // ===== Cross-qs reduction through smem (S region is dead now) =====
    __syncthreads();
    unsigned long long* red = (unsigned long long*)smem;  // [(mp*6+p)*265 + qs*33 + mg]
    #pragma unroll
    for (int mp = 0; mp < 4; ++mp)
        #pragma unroll
        for (int p = 0; p < 6; ++p)
            red[(mp * 6 + p) * 265 + qs * 33 + mg] = acc[mp][p];
    __syncthreads();

    const float inv_k = 1.0f / (float)KN;
    #pragma unroll
    for (int oi = 0; oi < 3; ++oi) {
        const int id = oi * 256 + tid;       // 0..767 = (node-pair p, m)
        const int m  = id & 127;             // consecutive m -> coalesced STG
        const int p  = id >> 7;              // node-pair 0..5
        const int mgr = m >> 2;
        const int mpr = m & 3;
        float a = 0.f, b = 0.f;
        #pragma unroll
        for (int q2 = 0; q2 < 8; ++q2) {
            float x, y;
            unpk2(x, y, red[(mpr * 6 + p) * 265 + q2 * 33 + mgr]);
            a += x; b += y;
        }
        const int i0 = base + 2 * p;
        if (i0 < N)     out[(size_t)i0 * F + m]       = a * inv_k;
        if (i0 + 1 < N) out[(size_t)(i0 + 1) * F + m] = b * inv_k;
    }
}

// ---------- launch ----------
extern "C" void kernel_launch(void* const* d_in, const int* in_sizes, int n_in,
                              void* d_out, int out_size) {
    // Identify inputs by element count:
    //   w = F*F*E = 262144, edges = largest, nodes = edges/4, nlist = edges/16.
    int iw = -1, ie = -1, ino = -1, inl = -1;
    long long emax = -1;
    for (int t = 0; t < n_in; ++t)
        if (in_sizes[t] == F * F * E) iw = t;
    for (int t = 0; t < n_in; ++t)
        if (t != iw && (long long)in_sizes[t] > emax) { emax = in_sizes[t]; ie = t; }
    for (int t = 0; t < n_in; ++t) {
        if (t == iw || t == ie) continue;
        if ((long long)in_sizes[t] * 4 == emax)  ino = t;
        if ((long long)in_sizes[t] * 16 == emax) inl = t;
    }
    if (iw < 0 || ie < 0 || ino < 0 || inl < 0) { ino = 0; inl = 1; ie = 2; iw = 3; }

    const float* nodes = (const float*)d_in[ino];
    const void*  nlist = d_in[inl];
    const float* edges = (const float*)d_in[ie];
    const float* w     = (const float*)d_in[iw];
    float*       out   = (float*)d_out;

    const int N = in_sizes[ino] / F;

    setup_kernel<<<(Q * F + NT - 1) / NT, NT>>>(w, (const int*)nlist);

    cudaFuncSetAttribute(mp_kernel,
                         cudaFuncAttributeMaxDynamicSharedMemorySize,
                         SMEM_BYTES);
    const int blocks = (N + MT - 1) / MT;
    mp_kernel<<<blocks, NT, SMEM_BYTES>>>(nodes, nlist, edges, out, N);
}

// round 9
// speedup vs baseline: 2.3227x; 2.3227x over previous
#include <cuda_runtime.h>
#include <cuda_fp16.h>
#include <cstdint>

#define F    128
#define E    16
#define KN   32
#define QD   2048          // flattened contraction dim, q' = l*16 + n
#define NROWS_PAD 50048    // 391 * 128 (zero-init tail covers last GEMM tile)

#define TB   128           // GEMM tile rows (nodes)
#define KC   64            // halves per K chunk (128 B per row)
#define NCH  (QD / KC)     // 32 chunks
#define ASTR 144           // smem row stride bytes (16B aligned, ldmatrix conflict-free)

// ---------------- device globals (static scratch: allocation-free) ----------------
__device__ __half g_W2h[F * QD];                    // W'[m][q'] fp16, 512 KB
__device__ __half g_S[(size_t)NROWS_PAD * QD];      // S[node][q'] fp16, 205 MB (zero-init)
__device__ int    g_is64;

// ---------------- packed f32x2 helpers ----------------
__device__ __forceinline__ void ffma2(unsigned long long& d,
                                      unsigned long long a,
                                      unsigned long long b) {
    asm("fma.rn.f32x2 %0, %1, %2, %0;" : "+l"(d) : "l"(a), "l"(b));
}
__device__ __forceinline__ unsigned long long pk2(float x, float y) {
    unsigned long long r;
    asm("mov.b64 %0, {%1, %2};" : "=l"(r) : "f"(x), "f"(y));
    return r;
}
__device__ __forceinline__ void unpk2(float& x, float& y, unsigned long long v) {
    asm("mov.b64 {%0, %1}, %2;" : "=f"(x), "=f"(y) : "l"(v));
}

// ---------------- mma.sync / ldmatrix helpers (compute_103-safe) ----------------
__device__ __forceinline__ uint32_t smem_u32(const void* p) {
    uint32_t a;
    asm("{ .reg .u64 t; cvta.to.shared.u64 t, %1; cvt.u32.u64 %0, t; }" : "=r"(a) : "l"(p));
    return a;
}
__device__ __forceinline__ void ldm_x4(uint32_t* r, uint32_t addr) {
    asm volatile("ldmatrix.sync.aligned.m8n8.x4.shared.b16 {%0,%1,%2,%3}, [%4];"
                 : "=r"(r[0]), "=r"(r[1]), "=r"(r[2]), "=r"(r[3]) : "r"(addr));
}
__device__ __forceinline__ void mma16816(float* c,
                                         uint32_t a0, uint32_t a1, uint32_t a2, uint32_t a3,
                                         uint32_t b0, uint32_t b1) {
    asm volatile(
        "mma.sync.aligned.m16n8k16.row.col.f32.f16.f16.f32 "
        "{%0,%1,%2,%3}, {%4,%5,%6,%7}, {%8,%9}, {%0,%1,%2,%3};"
        : "+f"(c[0]), "+f"(c[1]), "+f"(c[2]), "+f"(c[3])
        : "r"(a0), "r"(a1), "r"(a2), "r"(a3), "r"(b0), "r"(b1));
}

// ---------------- kernel 1: setup (W'[m][q'] fp16 + nlist dtype detect) ----------------
__global__ void setup_kernel(const float* __restrict__ w,
                             const int* __restrict__ nl) {
    if (blockIdx.x == 0 && threadIdx.x < 32) {
        int odd_nonzero = (threadIdx.x < 16) ? (nl[2 * threadIdx.x + 1] != 0) : 0;
        unsigned any = __ballot_sync(0xffffffffu, odd_nonzero);
        if (threadIdx.x == 0) g_is64 = (any == 0u) ? 1 : 0;
    }
    int o = blockIdx.x * blockDim.x + threadIdx.x;   // o = m*2048 + l*16 + n
    if (o >= F * QD) return;
    int m = o >> 11;
    int r = o & 2047;
    int l = r >> 4;
    int n = r & 15;
    g_W2h[o] = __float2half_rn(w[((l << 7) + m) * E + n]);
}

// ---------------- kernel 2: gather + edge contraction -> g_S fp16 ----------------
__global__ void __launch_bounds__(256)
s_kernel(const float* __restrict__ nodes,
         const void* __restrict__ nlist_raw,
         const float* __restrict__ edges,
         int N) {
    __shared__ float eb[2 * KN * E];   // 4 KB edge staging (2 nodes)
    __shared__ int   ib[2 * KN];

    const int tid  = threadIdx.x;
    const int l    = tid & (F - 1);
    const int sub  = tid >> 7;          // 0/1
    const int base = blockIdx.x * 16;
    const int is64 = g_is64;

    const long long* nl64 = (const long long*)nlist_raw;
    const int*       nl32 = (const int*)nlist_raw;

    for (int it = 0; it < 8; ++it) {
        const int v = it * 2 + sub;
        const int i = base + v;
        const bool valid = (i < N);

        __syncthreads();
        if (valid) {
            ((float4*)(eb + sub * (KN * E)))[l] =
                ((const float4*)(edges + (size_t)i * (KN * E)))[l];
            if (l < KN) {
                int nb = is64 ? (int)nl64[(size_t)i * KN + l]
                              :      nl32[(size_t)i * KN + l];
                ib[sub * KN + l] = nb;
            }
        }
        __syncthreads();

        if (valid) {
            unsigned long long acc[E / 2];
            #pragma unroll
            for (int p = 0; p < E / 2; ++p) acc[p] = 0ull;

            const float* ebs = eb + sub * (KN * E);
            const int*   ibs = ib + sub * KN;

            #pragma unroll
            for (int j0 = 0; j0 < KN; j0 += 8) {
                float x[8];
                #pragma unroll
                for (int u = 0; u < 8; ++u) {
                    int nb = ibs[j0 + u];
                    x[u] = nodes[(size_t)nb * F + l];   // coalesced over l
                }
                #pragma unroll
                for (int u = 0; u < 8; ++u) {
                    unsigned long long xx = pk2(x[u], x[u]);
                    const ulonglong2* ep2 = (const ulonglong2*)(ebs + (j0 + u) * E);
                    const ulonglong2 e01 = ep2[0];
                    const ulonglong2 e23 = ep2[1];
                    const ulonglong2 e45 = ep2[2];
                    const ulonglong2 e67 = ep2[3];
                    ffma2(acc[0], xx, e01.x);  ffma2(acc[1], xx, e01.y);
                    ffma2(acc[2], xx, e23.x);  ffma2(acc[3], xx, e23.y);
                    ffma2(acc[4], xx, e45.x);  ffma2(acc[5], xx, e45.y);
                    ffma2(acc[6], xx, e67.x);  ffma2(acc[7], xx, e67.y);
                }
            }

            // fp16 pack, q' = l*16 + n contiguous: 32 B per thread, fully coalesced
            unsigned int h[8];
            #pragma unroll
            for (int p = 0; p < E / 2; ++p) {
                float a, b;
                unpk2(a, b, acc[p]);
                __half2 hh = __floats2half2_rn(a, b);
                h[p] = *(unsigned int*)&hh;
            }
            uint4* dst = (uint4*)(g_S + ((size_t)i * QD + l * 16));
            dst[0] = make_uint4(h[0], h[1], h[2], h[3]);
            dst[1] = make_uint4(h[4], h[5], h[6], h[7]);
        }
    }
}

// ---------------- kernel 3: mma.sync f16 GEMM: out = (1/K) * S @ W'^T ----------------
__global__ void __launch_bounds__(256)
gemm_kernel(float* __restrict__ out, int N) {
    __shared__ __align__(16) char smA[TB * ASTR];   // 18432 B
    __shared__ __align__(16) char smB[F * ASTR];    // 18432 B

    const int tid  = threadIdx.x;
    const int wid  = tid >> 5;
    const int lane = tid & 31;
    const int wm   = wid >> 1;        // 0..3 -> rows [wm*32, +32)
    const int wn   = wid & 1;         // 0..1 -> cols [wn*64, +64)

    const size_t tile_base = (size_t)blockIdx.x * TB;
    const char* Ag = (const char*)(g_S + tile_base * QD);   // rows 4096 B apart
    const char* Bg = (const char*)g_W2h;                    // rows 4096 B apart

    // global->smem staging mapping: row0 = tid>>3 (+32*r4), seg = tid&7 (16 B)
    const int arow = tid >> 3;
    const int aseg = tid & 7;

    // ldmatrix per-lane base addresses (row = lane&15, seg = lane>>4)
    const int lrow = lane & 15;
    const int lseg = lane >> 4;
    const uint32_t smbA = smem_u32(smA);
    const uint32_t smbB = smem_u32(smB);
    const uint32_t aAddr0 = smbA + (uint32_t)(wm * 32 + lrow) * ASTR + lseg * 16;
    const uint32_t bAddr0 = smbB + (uint32_t)(wn * 64 + lrow) * ASTR + lseg * 16;

    float acc[2][8][4];
    #pragma unroll
    for (int mf = 0; mf < 2; ++mf)
        #pragma unroll
        for (int nf = 0; nf < 8; ++nf)
            #pragma unroll
            for (int x = 0; x < 4; ++x) acc[mf][nf][x] = 0.f;

    uint4 ra[4], rb[4];
    // prefetch chunk 0
    #pragma unroll
    for (int r4 = 0; r4 < 4; ++r4) {
        size_t roff = (size_t)(arow + r4 * 32) * 4096 + aseg * 16;
        ra[r4] = *(const uint4*)(Ag + roff);
        rb[r4] = *(const uint4*)(Bg + roff);
    }

    for (int c = 0; c < NCH; ++c) {
        // store chunk c
        #pragma unroll
        for (int r4 = 0; r4 < 4; ++r4) {
            uint32_t soff = (uint32_t)(arow + r4 * 32) * ASTR + aseg * 16;
            *(uint4*)(smA + soff) = ra[r4];
            *(uint4*)(smB + soff) = rb[r4];
        }
        __syncthreads();

        // prefetch chunk c+1 (LDGs in flight under the MMAs)
        if (c + 1 < NCH) {
            #pragma unroll
            for (int r4 = 0; r4 < 4; ++r4) {
                size_t roff = (size_t)(arow + r4 * 32) * 4096 + (c + 1) * 128 + aseg * 16;
                ra[r4] = *(const uint4*)(Ag + roff);
                rb[r4] = *(const uint4*)(Bg + roff);
            }
        }

        // compute: 4 k16 steps over this 64-half chunk
        #pragma unroll
        for (int ks = 0; ks < 4; ++ks) {
            const uint32_t kb = ks * 32;   // byte offset of k16 group
            uint32_t a0[4], a1[4];
            ldm_x4(a0, aAddr0 + kb);                    // rows wm*32+0..15
            ldm_x4(a1, aAddr0 + 16 * ASTR + kb);        // rows wm*32+16..31
            #pragma unroll
            for (int nf16 = 0; nf16 < 4; ++nf16) {
                uint32_t b4[4];
                ldm_x4(b4, bAddr0 + (uint32_t)nf16 * 16 * ASTR + kb);
                // n8 tile 0: {b4[0], b4[2]}, n8 tile 1: {b4[1], b4[3]}
                mma16816(acc[0][nf16 * 2 + 0], a0[0], a0[1], a0[2], a0[3], b4[0], b4[2]);
                mma16816(acc[0][nf16 * 2 + 1], a0[0], a0[1], a0[2], a0[3], b4[1], b4[3]);
                mma16816(acc[1][nf16 * 2 + 0], a1[0], a1[1], a1[2], a1[3], b4[0], b4[2]);
                mma16816(acc[1][nf16 * 2 + 1], a1[0], a1[1], a1[2], a1[3], b4[1], b4[3]);
            }
        }
        __syncthreads();
    }

    // epilogue: acc -> out, scaled by 1/K
    const float inv_k = 1.0f / (float)KN;
    const int rbase = (int)tile_base + wm * 32 + (lane >> 2);
    const int cbase = wn * 64 + (lane & 3) * 2;
    #pragma unroll
    for (int mf = 0; mf < 2; ++mf) {
        const int r0 = rbase + mf * 16;
        #pragma unroll
        for (int nf = 0; nf < 8; ++nf) {
            const int col = cbase + nf * 8;
            if (r0 < N) {
                float2 o0 = make_float2(acc[mf][nf][0] * inv_k, acc[mf][nf][1] * inv_k);
                *(float2*)(out + (size_t)r0 * F + col) = o0;
            }
            if (r0 + 8 < N) {
                float2 o1 = make_float2(acc[mf][nf][2] * inv_k, acc[mf][nf][3] * inv_k);
                *(float2*)(out + (size_t)(r0 + 8) * F + col) = o1;
            }
        }
    }
}

// ---------------- launch ----------------
extern "C" void kernel_launch(void* const* d_in, const int* in_sizes, int n_in,
                              void* d_out, int out_size) {
    // Identify inputs by element count:
    //   w = F*F*E = 262144, edges = largest, nodes = edges/4, nlist = edges/16.
    int iw = -1, ie = -1, ino = -1, inl = -1;
    long long emax = -1;
    for (int t = 0; t < n_in; ++t)
        if (in_sizes[t] == F * F * E) iw = t;
    for (int t = 0; t < n_in; ++t)
        if (t != iw && (long long)in_sizes[t] > emax) { emax = in_sizes[t]; ie = t; }
    for (int t = 0; t < n_in; ++t) {
        if (t == iw || t == ie) continue;
        if ((long long)in_sizes[t] * 4 == emax)  ino = t;
        if ((long long)in_sizes[t] * 16 == emax) inl = t;
    }
    if (iw < 0 || ie < 0 || ino < 0 || inl < 0) { ino = 0; inl = 1; ie = 2; iw = 3; }

    const float* nodes = (const float*)d_in[ino];
    const void*  nlist = d_in[inl];
    const float* edges = (const float*)d_in[ie];
    const float* w     = (const float*)d_in[iw];
    float*       out   = (float*)d_out;

    const int N = in_sizes[ino] / F;

    setup_kernel<<<(F * QD + 255) / 256, 256>>>(w, (const int*)nlist);
    s_kernel<<<(N + 15) / 16, 256>>>(nodes, nlist, edges, N);

    const int tiles = (N + TB - 1) / TB;
    gemm_kernel<<<tiles, 256>>>(out, N);
}